// round 16
// baseline (speedup 1.0000x reference)
#include <cuda_runtime.h>
#include <cuda_bf16.h>
#include <math.h>
#include <stdint.h>

// ---------------- problem constants ----------------
#define NN 102400
#define EE 819200
#define DD 120
#define HH 200
#define CCC 320
#define LL 400
#define BB 256
#define NSTEPS 8
#define M2 25344          // BB*99
#define MP 50688          // BB*198

// packed-layout row widths (main [hi|lo] + one 64-wide mixed tail chunk)
#define WH 448            // K=200: 2*192 + 64
#define WS 832            // K=400: 2*384 + 64
#define WC 640            // K=320: 2*320 (exact, no tail)

// ---------------- PTX helpers ----------------
__device__ __forceinline__ uint32_t smem_u32(const void* p) {
    uint32_t a;
    asm("{ .reg .u64 t; cvta.to.shared.u64 t, %1; cvt.u32.u64 %0, t; }" : "=r"(a) : "l"(p));
    return a;
}
#define CP_ASYNC16(dst, src) \
    asm volatile("cp.async.cg.shared.global [%0], [%1], 16;" :: "r"(dst), "l"(src) : "memory")
#define CP_ASYNC16Z(dst, src, sz) \
    asm volatile("cp.async.cg.shared.global [%0], [%1], 16, %2;" :: "r"(dst), "l"(src), "r"(sz) : "memory")
#define CP_COMMIT() asm volatile("cp.async.commit_group;" ::: "memory")
#define CP_WAIT(n)  asm volatile("cp.async.wait_group %0;" :: "n"(n) : "memory")
#define LDSM4(r, addr) \
    asm volatile("ldmatrix.sync.aligned.m8n8.x4.shared.b16 {%0,%1,%2,%3}, [%4];" \
        : "=r"((r)[0]), "=r"((r)[1]), "=r"((r)[2]), "=r"((r)[3]) : "r"(addr))
#define MMA16816(d, a, bx, by) \
    asm volatile("mma.sync.aligned.m16n8k16.row.col.f32.bf16.bf16.f32 " \
        "{%0,%1,%2,%3}, {%4,%5,%6,%7}, {%8,%9}, {%0,%1,%2,%3};" \
        : "+f"((d)[0]), "+f"((d)[1]), "+f"((d)[2]), "+f"((d)[3]) \
        : "r"((a)[0]), "r"((a)[1]), "r"((a)[2]), "r"((a)[3]), "r"(bx), "r"(by))

__device__ __forceinline__ void split2(float v, __nv_bfloat16& hi, __nv_bfloat16& lo) {
    hi = __float2bfloat16(v);
    lo = __float2bfloat16(v - __bfloat162float(hi));
}
__device__ __forceinline__ uint32_t packbf(__nv_bfloat16 a, __nv_bfloat16 b) {
    return (uint32_t)__bfloat16_as_ushort(a) | ((uint32_t)__bfloat16_as_ushort(b) << 16);
}
__device__ __forceinline__ void split_pair(float v0, float v1, uint32_t& hiw, uint32_t& low) {
    __nv_bfloat16 h0, l0, h1, l1;
    split2(v0, h0, l0);
    split2(v1, h1, l1);
    hiw = packbf(h0, h1);
    low = packbf(l0, l1);
}
__device__ __forceinline__ float fsigmoid(float x) {
    return __fdividef(1.f, 1.f + __expf(-x));
}
__device__ __forceinline__ float ftanh(float x) {
    return 1.f - __fdividef(2.f, __expf(2.f * x) + 1.f);
}

// ---------------- scratch ----------------
__device__ __align__(256) float g_h0[NN * HH];
__device__ __align__(256) float g_h1[NN * HH];
__device__ __align__(256) __nv_bfloat16 g_h0s[(NN + 2) * WH];
__device__ __align__(256) __nv_bfloat16 g_h1s[(NN + 2) * WH];
__device__ __align__(256) __nv_bfloat16 g_ss[NN * WS];
__device__ __align__(256) __nv_bfloat16 g_as[NN * WH];
__device__ __align__(256) float g_gi[NN * 600];
__device__ __align__(256) float g_gh[NN * 600];
__device__ int g_cnt[2 * NN];
__device__ int g_rowptr[2 * NN + 1];
__device__ int g_rowfill[2 * NN];
__device__ int g_col[EE];
__device__ int g_part[200];
__device__ int g_pref[200];

__device__ __align__(256) __nv_bfloat16 g_wcat_s[200 * WS];
__device__ __align__(256) __nv_bfloat16 g_wih_s[600 * WH];
__device__ __align__(256) __nv_bfloat16 g_whh_s[600 * WH];
__device__ __align__(256) __nv_bfloat16 g_myw_s[256 * WH];
__device__ __align__(256) __nv_bfloat16 g_mzw_s[256 * WC];
__device__ __align__(256) __nv_bfloat16 g_c1p[200 * 3 * WH];
__device__ __align__(256) __nv_bfloat16 g_c2p[200 * WH];
__device__ __align__(256) __nv_bfloat16 g_cc1p[320 * 3 * WC];
__device__ __align__(256) __nv_bfloat16 g_cc2p[320 * WC];

__device__ __align__(256) __nv_bfloat16 g_xcat[(NN + 2) * WC];
__device__ __align__(256) float g_y1g[NN * 200];
__device__ __align__(256) float g_z1g[NN * 320];
__device__ __align__(256) __nv_bfloat16 g_y1s[(MP + 2) * WH];
__device__ __align__(256) __nv_bfloat16 g_z1s[(MP + 2) * WC];
__device__ __align__(256) float g_y2g[MP * 200];
__device__ __align__(256) float g_z2g[MP * 320];
__device__ __align__(256) __nv_bfloat16 g_y2ps[M2 * WH];
__device__ __align__(256) __nv_bfloat16 g_z2ps[M2 * WC];
__device__ __align__(256) float g_yp[M2 * 256];
__device__ __align__(256) float g_zp[M2 * 256];
__device__ float g_avg[BB * 256];
__device__ float g_m1[BB * 128];
__device__ float g_m2[BB * 64];
__device__ float g_hf[BB * 128];

// ---------------- HMMA split-bf16 GEMM, mixed-tail chunks, 3-stage pipe ----
// (exact R13/R15 hot loop: no runtime predicates inside)
#define ROWB 144
template<int KF, int REM, int NKW, int EPI>
__global__ void __launch_bounds__(256, 2)
gemm_mma(const __nv_bfloat16* __restrict__ A_, int lda,
         const __nv_bfloat16* __restrict__ B_, int ldb, int Ncols,
         float* __restrict__ C_, int ldc, const float* __restrict__ bias_,
         __nv_bfloat16* __restrict__ OS,
         const int* __restrict__ cc0, const int* __restrict__ cc1,
         const float* __restrict__ b1,
         const __nv_bfloat16* A2, const __nv_bfloat16* B2,
         float* C2, const float* bias2) {
    constexpr int CF = KF / 64;
    constexpr int PER = 3 * CF + REM;
    constexpr int NCH = NKW * PER;
    constexpr int W = 2 * KF + REM * 64;
    constexpr int APT = 2 * CF + REM;
    constexpr int STG = 128 * ROWB;
    constexpr int BBASE = 3 * STG;
    extern __shared__ char smem[];
    const uint32_t sb = smem_u32(smem);
    const int tid = threadIdx.x, lane = tid & 31, wid = tid >> 5;
    const int m0 = blockIdx.y * 128, n0 = blockIdx.x * 128;
    const int wm = wid >> 1, wn = wid & 1;

    const __nv_bfloat16* A = A_;
    const __nv_bfloat16* Bw = B_;
    float* C = C_;
    const float* bias = bias_;
    if (blockIdx.z == 1) { A = A2; Bw = B2; C = C2; bias = bias2; }

    float acc[2][8][4];
#pragma unroll
    for (int i = 0; i < 2; i++)
#pragma unroll
        for (int j = 0; j < 8; j++)
#pragma unroll
            for (int k = 0; k < 4; k++) acc[i][j][k] = 0.f;

    auto chunk_map = [&](int i, int& aoff, int& boff, int& kwv, bool& anew, int& aid) {
        int kw = i / PER;
        int r = i - kw * PER;
        int al;
        if (r < 2 * CF) {
            int pi = r >> 1;
            anew = ((r & 1) == 0);
            al = pi;
            aoff = pi * 64;
            boff = ((r & 1) ? KF : 0) + pi * 64;
        } else if (r < 3 * CF) {
            int c = r - 2 * CF;
            anew = true;
            al = CF + c;
            aoff = KF + c * 64;
            boff = c * 64;
        } else {
            anew = true;
            al = 2 * CF;
            aoff = 2 * KF;
            boff = 2 * KF;
        }
        kwv = kw;
        aid = kw * APT + al;
        boff += kw * W;
    };

    auto load_stage = [&](int i) {
        int aoff, boff, kwv, aid; bool anew;
        chunk_map(i, aoff, boff, kwv, anew, aid);
        if (anew) {
            uint32_t sA = sb + (aid % 3) * STG;
#pragma unroll
            for (int t = 0; t < 4; t++) {
                int idx = tid + t * 256;
                int row = idx >> 3, j = idx & 7;
                const __nv_bfloat16* src = A + (size_t)(m0 + row + kwv) * lda + aoff + j * 8;
                CP_ASYNC16(sA + row * ROWB + j * 16, src);
            }
        }
        uint32_t sB = sb + BBASE + (i % 3) * STG;
#pragma unroll
        for (int t = 0; t < 4; t++) {
            int idx = tid + t * 256;
            int row = idx >> 3, j = idx & 7;
            int n = n0 + row;
            int ok = (n < Ncols);
            const __nv_bfloat16* src = Bw + (size_t)(ok ? n : 0) * ldb + boff + j * 8;
            CP_ASYNC16Z(sB + row * ROWB + j * 16, src, ok ? 16 : 0);
        }
        CP_COMMIT();
    };

    const uint32_t aLane = (uint32_t)((wm * 32 + (lane & 15)) * ROWB + ((lane >> 4) * 8) * 2);
    const uint32_t bLane = (uint32_t)((wn * 64 + (lane & 7) + ((lane >> 4) * 8)) * ROWB +
                                      (((lane >> 3) & 1) * 8) * 2);

    load_stage(0);
    load_stage(1);
    for (int i = 0; i < NCH; i++) {
        if (i + 1 < NCH) { CP_WAIT(1); }
        else             { CP_WAIT(0); }
        __syncthreads();
        int aoff, boff, kwv, aid; bool anew;
        chunk_map(i, aoff, boff, kwv, anew, aid);
        uint32_t aB = sb + (aid % 3) * STG + aLane;
        uint32_t bB = sb + BBASE + (i % 3) * STG + bLane;
#pragma unroll
        for (int ks = 0; ks < 4; ks++) {
            uint32_t a0[4], a1[4], bf[4][4];
            LDSM4(a0, aB + ks * 32);
            LDSM4(a1, aB + 16 * ROWB + ks * 32);
#pragma unroll
            for (int j = 0; j < 4; j++)
                LDSM4(bf[j], bB + j * 16 * ROWB + ks * 32);
#pragma unroll
            for (int j = 0; j < 4; j++) {
                MMA16816(acc[0][2 * j],     a0, bf[j][0], bf[j][1]);
                MMA16816(acc[0][2 * j + 1], a0, bf[j][2], bf[j][3]);
                MMA16816(acc[1][2 * j],     a1, bf[j][0], bf[j][1]);
                MMA16816(acc[1][2 * j + 1], a1, bf[j][2], bf[j][3]);
            }
        }
        if (i + 2 < NCH) load_stage(i + 2);
    }

    const int g = lane >> 2, tg = lane & 3;
#pragma unroll
    for (int mi = 0; mi < 2; mi++) {
        int mA = m0 + wm * 32 + mi * 16 + g;
#pragma unroll
        for (int nj = 0; nj < 8; nj++) {
            int n = n0 + wn * 64 + nj * 8 + tg * 2;
            float v0 = acc[mi][nj][0], v1 = acc[mi][nj][1];
            float v2 = acc[mi][nj][2], v3 = acc[mi][nj][3];
            if (EPI == 0 || EPI == 2) {
                if (n < Ncols) {
                    float bn = bias[n], bn1 = bias[n + 1];
                    v0 += bn; v1 += bn1; v2 += bn; v3 += bn1;
                    if (EPI == 2) {
                        v0 = fmaxf(v0, 0.f); v1 = fmaxf(v1, 0.f);
                        v2 = fmaxf(v2, 0.f); v3 = fmaxf(v3, 0.f);
                    }
                    *(float2*)&C[(size_t)mA * ldc + n] = make_float2(v0, v1);
                    *(float2*)&C[(size_t)(mA + 8) * ldc + n] = make_float2(v2, v3);
                }
            } else {
                if (n < 200) {
                    float bn = bias[n], bn1 = bias[n + 1];
                    float dn = b1[n], dn1 = b1[n + 1];
                    float q0a = (float)cc0[mA], q1a = (float)cc1[mA];
                    float q0b = (float)cc0[mA + 8], q1b = (float)cc1[mA + 8];
                    v0 += q0a * bn + q1a * dn;   v1 += q0a * bn1 + q1a * dn1;
                    v2 += q0b * bn + q1b * dn;   v3 += q0b * bn1 + q1b * dn1;
                    uint32_t hi0, lo0, hi1, lo1;
                    split_pair(v0, v1, hi0, lo0);
                    split_pair(v2, v3, hi1, lo1);
                    __nv_bfloat16* r0 = OS + (size_t)mA * WH;
                    __nv_bfloat16* r1 = OS + (size_t)(mA + 8) * WH;
                    if (n < 192) {
                        *(uint32_t*)&r0[n] = hi0;       *(uint32_t*)&r0[192 + n] = lo0;
                        *(uint32_t*)&r1[n] = hi1;       *(uint32_t*)&r1[192 + n] = lo1;
                    } else {
                        int q = n - 192;
                        *(uint32_t*)&r0[384 + q] = hi0; *(uint32_t*)&r0[392 + q] = lo0;
                        *(uint32_t*)&r0[400 + q] = hi0;
                        *(uint32_t*)&r1[384 + q] = hi1; *(uint32_t*)&r1[392 + q] = lo1;
                        *(uint32_t*)&r1[400 + q] = hi1;
                    }
                }
            }
        }
    }
}

// ---------------- preprocessing kernels ----------------
__global__ void k_init_h(const float* __restrict__ x, float* __restrict__ h,
                         __nv_bfloat16* __restrict__ hs0, __nv_bfloat16* __restrict__ hs1) {
    int idx = blockIdx.x * blockDim.x + threadIdx.x;
    if (idx >= (NN + 2) * WH) return;
    int n = idx / WH, j = idx - n * WH;
    __nv_bfloat16 z = __float2bfloat16(0.f);
    hs1[idx] = z;
    if (n >= NN) { hs0[idx] = z; return; }
    int ch = -1; bool ishi = true; bool firsthi = false;
    if (j < 192)      { ch = j; ishi = true; firsthi = true; }
    else if (j < 384) { ch = j - 192; ishi = false; }
    else {
        int p = j - 384;
        if (p < 8)       { ch = 192 + p; ishi = true; firsthi = true; }
        else if (p < 16) { ch = 192 + p - 8; ishi = false; }
        else if (p < 24) { ch = 192 + p - 16; ishi = true; }
    }
    if (ch < 0) { hs0[idx] = z; return; }
    float v = (ch < DD) ? x[(size_t)n * DD + ch] : 0.f;
    if (firsthi) h[(size_t)n * HH + ch] = v;
    __nv_bfloat16 hi, lo;
    split2(v, hi, lo);
    hs0[idx] = ishi ? hi : lo;
}

__global__ void k_zero_as(__nv_bfloat16* __restrict__ as_) {
    int idx = blockIdx.x * blockDim.x + threadIdx.x;
    if (idx >= NN * 20) return;
    int n = idx / 20, c = (idx - n * 20) * 2;
    *(uint32_t*)&as_[(size_t)n * WH + 408 + c] = 0;
}

__global__ void k_count(const int* __restrict__ eidx, const int* __restrict__ etyp,
                        int* __restrict__ cnt) {
    int e = blockIdx.x * blockDim.x + threadIdx.x;
    if (e >= EE) return;
    int d = eidx[EE + e] + (etyp[e] ? NN : 0);
    atomicAdd(&cnt[d], 1);
}

__global__ void k_scan1(const int* __restrict__ cnt, int* __restrict__ part) {
    __shared__ int sh[1024];
    int t = threadIdx.x;
    int v = cnt[blockIdx.x * 1024 + t];
    sh[t] = v;
    __syncthreads();
    for (int off = 512; off > 0; off >>= 1) {
        if (t < off) sh[t] += sh[t + off];
        __syncthreads();
    }
    if (t == 0) part[blockIdx.x] = sh[0];
}

__global__ void k_scan2(const int* __restrict__ part, int* __restrict__ pref,
                        int* __restrict__ rowptr) {
    __shared__ int sh[256];
    int t = threadIdx.x;
    int v = (t < 200) ? part[t] : 0;
    sh[t] = v;
    __syncthreads();
    for (int off = 1; off < 256; off <<= 1) {
        int u = (t >= off) ? sh[t - off] : 0;
        __syncthreads();
        sh[t] += u;
        __syncthreads();
    }
    if (t < 200) pref[t] = sh[t] - v;
    if (t == 0) rowptr[2 * NN] = EE;
}

__global__ void k_scan3(const int* __restrict__ cnt, const int* __restrict__ pref,
                        int* __restrict__ rowptr, int* __restrict__ rowfill) {
    __shared__ int sh[1024];
    int t = threadIdx.x;
    int i = blockIdx.x * 1024 + t;
    int v = cnt[i];
    sh[t] = v;
    __syncthreads();
    for (int off = 1; off < 1024; off <<= 1) {
        int u = (t >= off) ? sh[t - off] : 0;
        __syncthreads();
        sh[t] += u;
        __syncthreads();
    }
    int excl = sh[t] - v + pref[blockIdx.x];
    rowptr[i] = excl;
    rowfill[i] = excl;
}

__global__ void k_fill(const int* __restrict__ eidx, const int* __restrict__ etyp,
                       int* __restrict__ rowfill, int* __restrict__ col) {
    int e = blockIdx.x * blockDim.x + threadIdx.x;
    if (e >= EE) return;
    int d = eidx[EE + e] + (etyp[e] ? NN : 0);
    int p = atomicAdd(&rowfill[d], 1);
    col[p] = eidx[e];
}

__global__ void k_packw(const float* __restrict__ src, __nv_bfloat16* __restrict__ dst,
                        int O, int I, int KW) {
    int KFw = (I / 64) * 64;
    int rem = I - KFw;
    int Wd = 2 * KFw + (rem ? 64 : 0);
    int idx = blockIdx.x * blockDim.x + threadIdx.x;
    if (idx >= O * KW * Wd) return;
    int o = idx / (KW * Wd);
    int r = idx - o * (KW * Wd);
    int kw = r / Wd, j = r - kw * Wd;
    int ch = -1; bool ishi = true;
    if (j < KFw)          { ch = j; ishi = true; }
    else if (j < 2 * KFw) { ch = j - KFw; ishi = false; }
    else {
        int p = j - 2 * KFw;
        if (p < rem)          { ch = KFw + p; ishi = true; }
        else if (p < 2 * rem) { ch = KFw + p - rem; ishi = true; }
        else if (p < 3 * rem) { ch = KFw + p - 2 * rem; ishi = false; }
    }
    __nv_bfloat16 outv = __float2bfloat16(0.f);
    if (ch >= 0) {
        float v = src[((size_t)o * I + ch) * KW + kw];
        __nv_bfloat16 hi, lo;
        split2(v, hi, lo);
        outv = ishi ? hi : lo;
    }
    dst[(size_t)o * (KW * Wd) + (size_t)kw * Wd + j] = outv;
}

__global__ void k_wcat_pack(const float* __restrict__ gW, __nv_bfloat16* __restrict__ dst) {
    int idx = blockIdx.x * blockDim.x + threadIdx.x;
    if (idx >= 200 * WS) return;
    int o = idx / WS, j = idx - o * WS;
    int ch = -1; bool ishi = true;
    if (j < 384)      { ch = j; ishi = true; }
    else if (j < 768) { ch = j - 384; ishi = false; }
    else {
        int p = j - 768;
        if (p < 16)      { ch = 384 + p; ishi = true; }
        else if (p < 32) { ch = 384 + p - 16; ishi = true; }
        else if (p < 48) { ch = 384 + p - 32; ishi = false; }
    }
    __nv_bfloat16 outv = __float2bfloat16(0.f);
    if (ch >= 0) {
        float v = (ch < 200) ? gW[(size_t)o * 200 + ch]
                             : gW[(size_t)200 * 200 + (size_t)o * 200 + (ch - 200)];
        __nv_bfloat16 hi, lo;
        split2(v, hi, lo);
        outv = ishi ? hi : lo;
    }
    dst[idx] = outv;
}

// ---------------- gather: 64-thread group per (node, etype) -> WS rows ------
__global__ void k_gather(const float* __restrict__ h, const int* __restrict__ rowptr,
                         const int* __restrict__ col, __nv_bfloat16* __restrict__ s) {
    int gid = (blockIdx.x * blockDim.x + threadIdx.x) >> 6;
    int t = threadIdx.x & 63;
    if (gid >= 2 * NN) return;
    int node = (gid < NN) ? gid : gid - NN;
    int ty   = (gid < NN) ? 0 : 1;
    bool act = (t < 50);
    float4 a = make_float4(0.f, 0.f, 0.f, 0.f);
    int beg = rowptr[gid], end = rowptr[gid + 1];
    int e = beg;
    for (; e + 4 <= end; e += 4) {
        int c0 = __ldg(&col[e]), c1 = __ldg(&col[e + 1]);
        int c2 = __ldg(&col[e + 2]), c3 = __ldg(&col[e + 3]);
        if (act) {
            float4 v0 = __ldg(reinterpret_cast<const float4*>(h + (size_t)c0 * HH) + t);
            float4 v1 = __ldg(reinterpret_cast<const float4*>(h + (size_t)c1 * HH) + t);
            float4 v2 = __ldg(reinterpret_cast<const float4*>(h + (size_t)c2 * HH) + t);
            float4 v3 = __ldg(reinterpret_cast<const float4*>(h + (size_t)c3 * HH) + t);
            a.x += v0.x + v1.x + v2.x + v3.x;
            a.y += v0.y + v1.y + v2.y + v3.y;
            a.z += v0.z + v1.z + v2.z + v3.z;
            a.w += v0.w + v1.w + v2.w + v3.w;
        }
    }
    if (e + 2 <= end) {   // MLP-2 chunk for remainder
        int c0 = __ldg(&col[e]), c1 = __ldg(&col[e + 1]);
        if (act) {
            float4 v0 = __ldg(reinterpret_cast<const float4*>(h + (size_t)c0 * HH) + t);
            float4 v1 = __ldg(reinterpret_cast<const float4*>(h + (size_t)c1 * HH) + t);
            a.x += v0.x + v1.x; a.y += v0.y + v1.y;
            a.z += v0.z + v1.z; a.w += v0.w + v1.w;
        }
        e += 2;
    }
    if (e < end) {
        int c0 = __ldg(&col[e]);
        if (act) {
            float4 v = __ldg(reinterpret_cast<const float4*>(h + (size_t)c0 * HH) + t);
            a.x += v.x; a.y += v.y; a.z += v.z; a.w += v.w;
        }
    }
    __nv_bfloat16* sr = s + (size_t)node * WS;
    if (act) {
        int ch = ty * 200 + 4 * t;
        uint32_t hiA, loA, hiB, loB;
        split_pair(a.x, a.y, hiA, loA);
        split_pair(a.z, a.w, hiB, loB);
        if (ch < 384) {
            *(uint32_t*)&sr[ch] = hiA;        *(uint32_t*)&sr[ch + 2] = hiB;
            *(uint32_t*)&sr[384 + ch] = loA;  *(uint32_t*)&sr[384 + ch + 2] = loB;
        } else {
            int q = ch - 384;
            *(uint32_t*)&sr[768 + q] = hiA;   *(uint32_t*)&sr[768 + q + 2] = hiB;
            *(uint32_t*)&sr[784 + q] = loA;   *(uint32_t*)&sr[784 + q + 2] = loB;
            *(uint32_t*)&sr[800 + q] = hiA;   *(uint32_t*)&sr[800 + q + 2] = hiB;
        }
    } else if (ty == 1 && t >= 50 && t < 54) {
        int c = 816 + (t - 50) * 4;
        *(uint32_t*)&sr[c] = 0;
        *(uint32_t*)&sr[c + 2] = 0;
    }
}

// float4 GRU, writes WH-layout split rows
__global__ void k_gru(const float* __restrict__ gi, const float* __restrict__ gh,
                      const float* __restrict__ h, float* __restrict__ hn,
                      __nv_bfloat16* __restrict__ hns) {
    int idx = blockIdx.x * blockDim.x + threadIdx.x;
    if (idx >= NN * 50) return;
    int n = idx / 50, c = (idx - n * 50) * 4;
    size_t base = (size_t)n * 600 + c;
    float4 ir  = *(const float4*)&gi[base];
    float4 iz  = *(const float4*)&gi[base + 200];
    float4 inn = *(const float4*)&gi[base + 400];
    float4 hr  = *(const float4*)&gh[base];
    float4 hz  = *(const float4*)&gh[base + 200];
    float4 hnn = *(const float4*)&gh[base + 400];
    float4 hv  = *(const float4*)&h[(size_t)n * HH + c];
    float4 o;
    o.x = (1.f - fsigmoid(iz.x + hz.x)) * ftanh(inn.x + fsigmoid(ir.x + hr.x) * hnn.x) + fsigmoid(iz.x + hz.x) * hv.x;
    o.y = (1.f - fsigmoid(iz.y + hz.y)) * ftanh(inn.y + fsigmoid(ir.y + hr.y) * hnn.y) + fsigmoid(iz.y + hz.y) * hv.y;
    o.z = (1.f - fsigmoid(iz.z + hz.z)) * ftanh(inn.z + fsigmoid(ir.z + hr.z) * hnn.z) + fsigmoid(iz.z + hz.z) * hv.z;
    o.w = (1.f - fsigmoid(iz.w + hz.w)) * ftanh(inn.w + fsigmoid(ir.w + hr.w) * hnn.w) + fsigmoid(iz.w + hz.w) * hv.w;
    *(float4*)&hn[(size_t)n * HH + c] = o;
    uint32_t hi0, lo0, hi1, lo1;
    split_pair(o.x, o.y, hi0, lo0);
    split_pair(o.z, o.w, hi1, lo1);
    __nv_bfloat16* hp = hns + (size_t)n * WH;
    if (c < 192) {
        *(uint32_t*)&hp[c] = hi0;        *(uint32_t*)&hp[c + 2] = hi1;
        *(uint32_t*)&hp[192 + c] = lo0;  *(uint32_t*)&hp[192 + c + 2] = lo1;
    } else {
        int q = c - 192;
        *(uint32_t*)&hp[384 + q] = hi0;  *(uint32_t*)&hp[384 + q + 2] = hi1;
        *(uint32_t*)&hp[392 + q] = lo0;  *(uint32_t*)&hp[392 + q + 2] = lo1;
        *(uint32_t*)&hp[400 + q] = hi0;  *(uint32_t*)&hp[400 + q + 2] = hi1;
    }
}

// concat(x, h) -> WC rows (K=320 exact, [hi|lo])
__global__ void k_catsplit(const float* __restrict__ x, const float* __restrict__ h,
                           __nv_bfloat16* __restrict__ dst) {
    int idx = blockIdx.x * blockDim.x + threadIdx.x;
    if (idx >= (NN + 2) * 160) return;
    int n = idx / 160, c = (idx - n * 160) * 2;
    float v0 = 0.f, v1 = 0.f;
    if (n < NN) {
        if (c < DD) {
            float2 xv = *(const float2*)&x[(size_t)n * DD + c];
            v0 = xv.x; v1 = xv.y;
        } else {
            float2 hvv = *(const float2*)&h[(size_t)n * HH + (c - DD)];
            v0 = hvv.x; v1 = hvv.y;
        }
    }
    uint32_t hiw, low;
    split_pair(v0, v1, hiw, low);
    *(uint32_t*)&dst[(size_t)n * WC + c] = hiw;
    *(uint32_t*)&dst[(size_t)n * WC + 320 + c] = low;
}

__device__ __forceinline__ int map_wh(int j, bool& ishi) {
    if (j < 192)      { ishi = true;  return j; }
    if (j < 384)      { ishi = false; return j - 192; }
    int p = j - 384;
    if (p < 8)        { ishi = true;  return 192 + p; }
    if (p < 16)       { ishi = false; return 192 + p - 8; }
    if (p < 24)       { ishi = true;  return 192 + p - 16; }
    return -1;
}

__global__ void k_pool3y(const float* __restrict__ in, __nv_bfloat16* __restrict__ out) {
    int idx = blockIdx.x * blockDim.x + threadIdx.x;
    if (idx >= (MP + 2) * 224) return;
    int m = idx / 224, j = (idx - m * 224) * 2;
    bool ishi;
    int ch = map_wh(j, ishi);
    float v0 = 0.f, v1 = 0.f;
    if (m < MP && ch >= 0) {
        int b = m / 198, l = m - b * 198;
        size_t base = ((size_t)b * 400 + 2 * l) * 200 + ch;
        float2 p0 = *(const float2*)&in[base];
        float2 p1 = *(const float2*)&in[base + 200];
        float2 p2 = *(const float2*)&in[base + 400];
        v0 = fmaxf(fmaxf(p0.x, p1.x), p2.x);
        v1 = fmaxf(fmaxf(p0.y, p1.y), p2.y);
    }
    uint32_t hiw, low;
    split_pair(v0, v1, hiw, low);
    *(uint32_t*)&out[(size_t)m * WH + j] = ishi ? hiw : low;
}

__global__ void k_pool2y(const float* __restrict__ in, __nv_bfloat16* __restrict__ out) {
    int idx = blockIdx.x * blockDim.x + threadIdx.x;
    if (idx >= M2 * 224) return;
    int m = idx / 224, j = (idx - m * 224) * 2;
    bool ishi;
    int ch = map_wh(j, ishi);
    float v0 = 0.f, v1 = 0.f;
    if (ch >= 0) {
        int b = m / 99, l = m - b * 99;
        size_t base = ((size_t)b * 198 + 2 * l) * 200 + ch;
        float2 p0 = *(const float2*)&in[base];
        float2 p1 = *(const float2*)&in[base + 200];
        v0 = fmaxf(p0.x, p1.x);
        v1 = fmaxf(p0.y, p1.y);
    }
    uint32_t hiw, low;
    split_pair(v0, v1, hiw, low);
    *(uint32_t*)&out[(size_t)m * WH + j] = ishi ? hiw : low;
}

__global__ void k_pool3z(const float* __restrict__ in, __nv_bfloat16* __restrict__ out) {
    int idx = blockIdx.x * blockDim.x + threadIdx.x;
    if (idx >= (MP + 2) * 160) return;
    int m = idx / 160, c = (idx - m * 160) * 2;
    float v0 = 0.f, v1 = 0.f;
    if (m < MP) {
        int b = m / 198, l = m - b * 198;
        size_t base = ((size_t)b * 400 + 2 * l) * 320 + c;
        float2 p0 = *(const float2*)&in[base];
        float2 p1 = *(const float2*)&in[base + 320];
        float2 p2 = *(const float2*)&in[base + 640];
        v0 = fmaxf(fmaxf(p0.x, p1.x), p2.x);
        v1 = fmaxf(fmaxf(p0.y, p1.y), p2.y);
    }
    uint32_t hiw, low;
    split_pair(v0, v1, hiw, low);
    *(uint32_t*)&out[(size_t)m * WC + c] = hiw;
    *(uint32_t*)&out[(size_t)m * WC + 320 + c] = low;
}

__global__ void k_pool2z(const float* __restrict__ in, __nv_bfloat16* __restrict__ out) {
    int idx = blockIdx.x * blockDim.x + threadIdx.x;
    if (idx >= M2 * 160) return;
    int m = idx / 160, c = (idx - m * 160) * 2;
    int b = m / 99, l = m - b * 99;
    size_t base = ((size_t)b * 198 + 2 * l) * 320 + c;
    float2 p0 = *(const float2*)&in[base];
    float2 p1 = *(const float2*)&in[base + 320];
    float v0 = fmaxf(p0.x, p1.x);
    float v1 = fmaxf(p0.y, p1.y);
    uint32_t hiw, low;
    split_pair(v0, v1, hiw, low);
    *(uint32_t*)&out[(size_t)m * WC + c] = hiw;
    *(uint32_t*)&out[(size_t)m * WC + 320 + c] = low;
}

__global__ void k_avg(const float* __restrict__ yp, const float* __restrict__ zp,
                      float* __restrict__ avg) {
    int idx = blockIdx.x * blockDim.x + threadIdx.x;
    if (idx >= BB * 64) return;
    int j = (idx & 63) * 4;
    int b = idx >> 6;
    float4 s = make_float4(0.f, 0.f, 0.f, 0.f);
    for (int l = 0; l < 99; l++) {
        size_t off = ((size_t)b * 99 + l) * 256 + j;
        float4 yv = *(const float4*)&yp[off];
        float4 zv = *(const float4*)&zp[off];
        s.x += yv.x * zv.x; s.y += yv.y * zv.y;
        s.z += yv.z * zv.z; s.w += yv.w * zv.w;
    }
    const float inv = 1.f / 99.f;
    s.x *= inv; s.y *= inv; s.z *= inv; s.w *= inv;
    *(float4*)&avg[(size_t)b * 256 + j] = s;
}

// ---------------- tiny SIMT head GEMM (optional 2nd output C2h) ----------
template<int EPI>
__global__ __launch_bounds__(256)
void gemm_tn(const float* __restrict__ A, const float* __restrict__ W,
             const float* __restrict__ bias, float* __restrict__ C,
             int M, int Nc, int K, float* __restrict__ C2h) {
    __shared__ float As[8][128];
    __shared__ float Ws[8][64];
    int tid = threadIdx.x;
    int m0 = blockIdx.y * 128;
    int n0 = blockIdx.x * 64;
    int msub = (tid >> 4) * 8;
    int nsub = (tid & 15) * 4;
    float acc[8][4];
#pragma unroll
    for (int i = 0; i < 8; i++)
#pragma unroll
        for (int j = 0; j < 4; j++) acc[i][j] = 0.f;
    int la_m = tid >> 1;
    int la_k = (tid & 1) * 4;
    int lw_n = tid >> 2;
    int lw_k = (tid & 3) * 2;
    for (int k0 = 0; k0 < K; k0 += 8) {
        float4 av = *(const float4*)(A + (size_t)(m0 + la_m) * K + k0 + la_k);
        As[la_k + 0][la_m] = av.x;
        As[la_k + 1][la_m] = av.y;
        As[la_k + 2][la_m] = av.z;
        As[la_k + 3][la_m] = av.w;
        float2 wv = make_float2(0.f, 0.f);
        if (n0 + lw_n < Nc)
            wv = *(const float2*)(W + (size_t)(n0 + lw_n) * K + k0 + lw_k);
        Ws[lw_k + 0][lw_n] = wv.x;
        Ws[lw_k + 1][lw_n] = wv.y;
        __syncthreads();
#pragma unroll
        for (int k = 0; k < 8; k++) {
            float4 a0 = *(const float4*)&As[k][msub];
            float4 a1 = *(const float4*)&As[k][msub + 4];
            float4 bv = *(const float4*)&Ws[k][nsub];
            float am[8] = {a0.x, a0.y, a0.z, a0.w, a1.x, a1.y, a1.z, a1.w};
            float bn[4] = {bv.x, bv.y, bv.z, bv.w};
#pragma unroll
            for (int i = 0; i < 8; i++)
#pragma unroll
                for (int j = 0; j < 4; j++) acc[i][j] += am[i] * bn[j];
        }
        __syncthreads();
    }
#pragma unroll
    for (int i = 0; i < 8; i++) {
        int m = m0 + msub + i;
#pragma unroll
        for (int j = 0; j < 4; j++) {
            int n = n0 + nsub + j;
            if (n < Nc) {
                float v = acc[i][j] + bias[n];
                if (EPI == 1) v = fmaxf(v, 0.f);
                C[(size_t)m * Nc + n] = v;
                if (C2h) C2h[(size_t)m * Nc + n] = v;
            }
        }
    }
}

// ---------------- launcher ----------------
extern "C" void kernel_launch(void* const* d_in, const int* in_sizes, int n_in,
                              void* d_out, int out_size) {
    const float* x    = (const float*)d_in[0];
    const int*   eidx = (const int*)d_in[1];
    const int*   etyp = (const int*)d_in[2];
    const float* ggnnW = (const float*)d_in[3];
    const float* ggnnB = (const float*)d_in[4];
    const float* Wih  = (const float*)d_in[5];
    const float* Whh  = (const float*)d_in[6];
    const float* bih  = (const float*)d_in[7];
    const float* bhh  = (const float*)d_in[8];
    const float* c1w  = (const float*)d_in[9];
    const float* c1b  = (const float*)d_in[10];
    const float* c2w  = (const float*)d_in[11];
    const float* c2b  = (const float*)d_in[12];
    const float* cc1w = (const float*)d_in[13];
    const float* cc1b = (const float*)d_in[14];
    const float* cc2w = (const float*)d_in[15];
    const float* cc2b = (const float*)d_in[16];
    const float* yw   = (const float*)d_in[17];
    const float* yb   = (const float*)d_in[18];
    const float* zw   = (const float*)d_in[19];
    const float* zb   = (const float*)d_in[20];
    const float* l1w  = (const float*)d_in[21];
    const float* l1b  = (const float*)d_in[22];
    const float* f1w  = (const float*)d_in[23];
    const float* f1b  = (const float*)d_in[24];
    const float* f2w  = (const float*)d_in[25];
    const float* f2b  = (const float*)d_in[26];
    const float* clsw = (const float*)d_in[27];
    const float* clsb = (const float*)d_in[28];
    float* out = (float*)d_out;

    void* p;
#define GET(name, sym, T) cudaGetSymbolAddress(&p, sym); T* name = (T*)p;
    GET(h0, g_h0, float) GET(h1, g_h1, float)
    GET(h0s, g_h0s, __nv_bfloat16) GET(h1s, g_h1s, __nv_bfloat16)
    GET(ss, g_ss, __nv_bfloat16) GET(as, g_as, __nv_bfloat16)
    GET(gi, g_gi, float) GET(gh, g_gh, float)
    GET(cnt, g_cnt, int) GET(rowptr, g_rowptr, int) GET(rowfill, g_rowfill, int)
    GET(colv, g_col, int) GET(part, g_part, int) GET(pref, g_pref, int)
    GET(wcs, g_wcat_s, __nv_bfloat16) GET(wis, g_wih_s, __nv_bfloat16) GET(whs, g_whh_s, __nv_bfloat16)
    GET(mys, g_myw_s, __nv_bfloat16) GET(mzs, g_mzw_s, __nv_bfloat16)
    GET(c1p, g_c1p, __nv_bfloat16) GET(c2p, g_c2p, __nv_bfloat16)
    GET(cc1p, g_cc1p, __nv_bfloat16) GET(cc2p, g_cc2p, __nv_bfloat16)
    GET(xcat, g_xcat, __nv_bfloat16)
    GET(y1g, g_y1g, float) GET(z1g, g_z1g, float)
    GET(y1s, g_y1s, __nv_bfloat16) GET(z1s, g_z1s, __nv_bfloat16)
    GET(y2g, g_y2g, float) GET(z2g, g_z2g, float)
    GET(y2ps, g_y2ps, __nv_bfloat16) GET(z2ps, g_z2ps, __nv_bfloat16)
    GET(yp, g_yp, float) GET(zp, g_zp, float) GET(avg, g_avg, float)
    GET(m1, g_m1, float) GET(m2v, g_m2, float) GET(hfv, g_hf, float)
#undef GET

    const int SMEM = 6 * 128 * ROWB;   // 110592 (3 A + 3 B stages)
    cudaFuncSetAttribute(gemm_mma<384, 1, 1, 1>, cudaFuncAttributeMaxDynamicSharedMemorySize, SMEM);
    cudaFuncSetAttribute(gemm_mma<192, 1, 1, 0>, cudaFuncAttributeMaxDynamicSharedMemorySize, SMEM);
    cudaFuncSetAttribute(gemm_mma<192, 1, 3, 2>, cudaFuncAttributeMaxDynamicSharedMemorySize, SMEM);
    cudaFuncSetAttribute(gemm_mma<192, 1, 1, 2>, cudaFuncAttributeMaxDynamicSharedMemorySize, SMEM);
    cudaFuncSetAttribute(gemm_mma<320, 0, 3, 2>, cudaFuncAttributeMaxDynamicSharedMemorySize, SMEM);
    cudaFuncSetAttribute(gemm_mma<320, 0, 1, 2>, cudaFuncAttributeMaxDynamicSharedMemorySize, SMEM);
    cudaFuncSetAttribute(gemm_mma<320, 0, 1, 0>, cudaFuncAttributeMaxDynamicSharedMemorySize, SMEM);

    // ---- preprocessing ----
    k_init_h<<<((NN + 2) * WH + 255) / 256, 256>>>(x, h0, h0s, h1s);
    k_zero_as<<<(NN * 20 + 255) / 256, 256>>>(as);
    cudaMemsetAsync(cnt, 0, 2 * NN * sizeof(int));
    k_count<<<EE / 256, 256>>>(eidx, etyp, cnt);
    k_scan1<<<200, 1024>>>(cnt, part);
    k_scan2<<<1, 256>>>(part, pref, rowptr);
    k_scan3<<<200, 1024>>>(cnt, pref, rowptr, rowfill);
    k_fill<<<EE / 256, 256>>>(eidx, etyp, rowfill, colv);
    k_wcat_pack<<<(200 * WS + 255) / 256, 256>>>(ggnnW, wcs);
    k_packw<<<(600 * WH + 255) / 256, 256>>>(Wih, wis, 600, 200, 1);
    k_packw<<<(600 * WH + 255) / 256, 256>>>(Whh, whs, 600, 200, 1);
    k_packw<<<(256 * WH + 255) / 256, 256>>>(yw, mys, 256, 200, 1);
    k_packw<<<(256 * WC + 255) / 256, 256>>>(zw, mzs, 256, 320, 1);
    k_packw<<<(200 * 3 * WH + 255) / 256, 256>>>(c1w, c1p, 200, 200, 3);
    k_packw<<<(200 * WH + 255) / 256, 256>>>(c2w, c2p, 200, 200, 1);
    k_packw<<<(320 * 3 * WC + 255) / 256, 256>>>(cc1w, cc1p, 320, 320, 3);
    k_packw<<<(320 * WC + 255) / 256, 256>>>(cc2w, cc2p, 320, 320, 1);

    // ---- GGNN steps ----
    for (int s = 0; s < NSTEPS; s++) {
        float* hin  = (s & 1) ? h1 : h0;
        float* hout = (s & 1) ? h0 : h1;
        __nv_bfloat16* hins  = (s & 1) ? h1s : h0s;
        __nv_bfloat16* houts = (s & 1) ? h0s : h1s;
        k_gather<<<2 * NN / 4, 256>>>(hin, rowptr, colv, ss);
        gemm_mma<384, 1, 1, 1><<<dim3(2, NN / 128), 256, SMEM>>>(
            ss, WS, wcs, WS, 200, nullptr, 0, ggnnB, as, cnt, cnt + NN, ggnnB + 200,
            ss, wcs, nullptr, ggnnB);
        gemm_mma<192, 1, 1, 0><<<dim3(5, NN / 128, 2), 256, SMEM>>>(
            as, WH, wis, WH, 600, gi, 600, bih, nullptr, nullptr, nullptr, nullptr,
            hins, whs, gh, bhh);
        k_gru<<<(NN * 50 + 255) / 256, 256>>>(gi, gh, hin, hout, houts);
    }
    // final h in h0 / h0s

    // ---- readout (all HMMA) ----
    k_catsplit<<<((NN + 2) * 160 + 255) / 256, 256>>>(x, h0, xcat);

    gemm_mma<192, 1, 3, 2><<<dim3(2, NN / 128), 256, SMEM>>>(
        h0s, WH, c1p, 3 * WH, 200, y1g, 200, c1b, nullptr, nullptr, nullptr, nullptr,
        h0s, c1p, y1g, c1b);
    k_pool3y<<<((MP + 2) * 224 + 255) / 256, 256>>>(y1g, y1s);
    gemm_mma<192, 1, 1, 2><<<dim3(2, MP / 128), 256, SMEM>>>(
        y1s, WH, c2p, WH, 200, y2g, 200, c2b, nullptr, nullptr, nullptr, nullptr,
        y1s, c2p, y2g, c2b);
    k_pool2y<<<(M2 * 224 + 255) / 256, 256>>>(y2g, y2ps);

    gemm_mma<320, 0, 3, 2><<<dim3(3, NN / 128), 256, SMEM>>>(
        xcat, WC, cc1p, 3 * WC, 320, z1g, 320, cc1b, nullptr, nullptr, nullptr, nullptr,
        xcat, cc1p, z1g, cc1b);
    k_pool3z<<<((MP + 2) * 160 + 255) / 256, 256>>>(z1g, z1s);
    gemm_mma<320, 0, 1, 2><<<dim3(3, MP / 128), 256, SMEM>>>(
        z1s, WC, cc2p, WC, 320, z2g, 320, cc2b, nullptr, nullptr, nullptr, nullptr,
        z1s, cc2p, z2g, cc2b);
    k_pool2z<<<(M2 * 160 + 255) / 256, 256>>>(z2g, z2ps);

    gemm_mma<192, 1, 1, 0><<<dim3(2, M2 / 128), 256, SMEM>>>(
        y2ps, WH, mys, WH, 256, yp, 256, yb, nullptr, nullptr, nullptr, nullptr,
        y2ps, mys, yp, yb);
    gemm_mma<320, 0, 1, 0><<<dim3(2, M2 / 128), 256, SMEM>>>(
        z2ps, WC, mzs, WC, 256, zp, 256, zb, nullptr, nullptr, nullptr, nullptr,
        z2ps, mzs, zp, zb);
    k_avg<<<(BB * 64 + 255) / 256, 256>>>(yp, zp, avg);

    // head: hf also written directly to out[512..], logits to out[0..512)
    gemm_tn<1><<<dim3(2, 2), 256>>>(avg, l1w, l1b, m1, BB, 128, 256, nullptr);
    gemm_tn<1><<<dim3(1, 2), 256>>>(m1, f1w, f1b, m2v, BB, 64, 128, nullptr);
    gemm_tn<1><<<dim3(2, 2), 256>>>(m2v, f2w, f2b, hfv, BB, 128, 64, out + BB * 2);
    gemm_tn<0><<<dim3(1, 2), 256>>>(hfv, clsw, clsb, out, BB, 2, 128, nullptr);
    (void)n_in; (void)in_sizes; (void)out_size;
}

// round 17
// speedup vs baseline: 1.0449x; 1.0449x over previous
#include <cuda_runtime.h>
#include <cuda_bf16.h>
#include <cuda_fp16.h>
#include <math.h>
#include <stdint.h>

// ---------------- problem constants ----------------
#define NN 102400
#define EE 819200
#define DD 120
#define HH 200
#define CCC 320
#define LL 400
#define BB 256
#define NSTEPS 8
#define M2 25344          // BB*99
#define MP 50688          // BB*198

// packed-layout row widths (main [hi|lo] + one 64-wide mixed tail chunk)
#define WH 448            // K=200: 2*192 + 64
#define WS 832            // K=400: 2*384 + 64
#define WC 640            // K=320: 2*320 (exact, no tail)

// ---------------- PTX helpers ----------------
__device__ __forceinline__ uint32_t smem_u32(const void* p) {
    uint32_t a;
    asm("{ .reg .u64 t; cvta.to.shared.u64 t, %1; cvt.u32.u64 %0, t; }" : "=r"(a) : "l"(p));
    return a;
}
#define CP_ASYNC16(dst, src) \
    asm volatile("cp.async.cg.shared.global [%0], [%1], 16;" :: "r"(dst), "l"(src) : "memory")
#define CP_ASYNC16Z(dst, src, sz) \
    asm volatile("cp.async.cg.shared.global [%0], [%1], 16, %2;" :: "r"(dst), "l"(src), "r"(sz) : "memory")
#define CP_COMMIT() asm volatile("cp.async.commit_group;" ::: "memory")
#define CP_WAIT(n)  asm volatile("cp.async.wait_group %0;" :: "n"(n) : "memory")
#define LDSM4(r, addr) \
    asm volatile("ldmatrix.sync.aligned.m8n8.x4.shared.b16 {%0,%1,%2,%3}, [%4];" \
        : "=r"((r)[0]), "=r"((r)[1]), "=r"((r)[2]), "=r"((r)[3]) : "r"(addr))
#define MMA16816(d, a, bx, by) \
    asm volatile("mma.sync.aligned.m16n8k16.row.col.f32.bf16.bf16.f32 " \
        "{%0,%1,%2,%3}, {%4,%5,%6,%7}, {%8,%9}, {%0,%1,%2,%3};" \
        : "+f"((d)[0]), "+f"((d)[1]), "+f"((d)[2]), "+f"((d)[3]) \
        : "r"((a)[0]), "r"((a)[1]), "r"((a)[2]), "r"((a)[3]), "r"(bx), "r"(by))

__device__ __forceinline__ void split2(float v, __nv_bfloat16& hi, __nv_bfloat16& lo) {
    hi = __float2bfloat16(v);
    lo = __float2bfloat16(v - __bfloat162float(hi));
}
__device__ __forceinline__ uint32_t packbf(__nv_bfloat16 a, __nv_bfloat16 b) {
    return (uint32_t)__bfloat16_as_ushort(a) | ((uint32_t)__bfloat16_as_ushort(b) << 16);
}
__device__ __forceinline__ void split_pair(float v0, float v1, uint32_t& hiw, uint32_t& low) {
    __nv_bfloat16 h0, l0, h1, l1;
    split2(v0, h0, l0);
    split2(v1, h1, l1);
    hiw = packbf(h0, h1);
    low = packbf(l0, l1);
}
__device__ __forceinline__ float fsigmoid(float x) {
    return __fdividef(1.f, 1.f + __expf(-x));
}
__device__ __forceinline__ float ftanh(float x) {
    return 1.f - __fdividef(2.f, __expf(2.f * x) + 1.f);
}
__device__ __forceinline__ float4 ldh4(const __half* p) {
    float2 a = __half22float2(*(const __half2*)p);
    float2 b = __half22float2(*(const __half2*)(p + 2));
    return make_float4(a.x, a.y, b.x, b.y);
}

// ---------------- scratch ----------------
__device__ __align__(256) float g_h0[NN * HH];
__device__ __align__(256) float g_h1[NN * HH];
__device__ __align__(256) __nv_bfloat16 g_h0s[(NN + 2) * WH];
__device__ __align__(256) __nv_bfloat16 g_h1s[(NN + 2) * WH];
__device__ __align__(256) __nv_bfloat16 g_ss[NN * WS];
__device__ __align__(256) __nv_bfloat16 g_as[NN * WH];
__device__ __align__(256) __half g_gi[NN * 600];
__device__ __align__(256) __half g_gh[NN * 600];
__device__ int g_cnt[2 * NN];
__device__ int g_rowptr[2 * NN + 1];
__device__ int g_rowfill[2 * NN];
__device__ int g_col[EE];
__device__ int g_part[200];
__device__ int g_pref[200];

__device__ __align__(256) __nv_bfloat16 g_wcat_s[200 * WS];
__device__ __align__(256) __nv_bfloat16 g_wih_s[600 * WH];
__device__ __align__(256) __nv_bfloat16 g_whh_s[600 * WH];
__device__ __align__(256) __nv_bfloat16 g_myw_s[256 * WH];
__device__ __align__(256) __nv_bfloat16 g_mzw_s[256 * WC];
__device__ __align__(256) __nv_bfloat16 g_c1p[200 * 3 * WH];
__device__ __align__(256) __nv_bfloat16 g_c2p[200 * WH];
__device__ __align__(256) __nv_bfloat16 g_cc1p[320 * 3 * WC];
__device__ __align__(256) __nv_bfloat16 g_cc2p[320 * WC];

__device__ __align__(256) __nv_bfloat16 g_xcat[(NN + 2) * WC];
__device__ __align__(256) float g_y1g[NN * 200];
__device__ __align__(256) float g_z1g[NN * 320];
__device__ __align__(256) __nv_bfloat16 g_y1s[(MP + 2) * WH];
__device__ __align__(256) __nv_bfloat16 g_z1s[(MP + 2) * WC];
__device__ __align__(256) float g_y2g[MP * 200];
__device__ __align__(256) float g_z2g[MP * 320];
__device__ __align__(256) __nv_bfloat16 g_y2ps[M2 * WH];
__device__ __align__(256) __nv_bfloat16 g_z2ps[M2 * WC];
__device__ __align__(256) float g_yp[M2 * 256];
__device__ __align__(256) float g_zp[M2 * 256];
__device__ float g_avg[BB * 256];
__device__ float g_m1[BB * 128];
__device__ float g_m2[BB * 64];
__device__ float g_hf[BB * 128];

// ---------------- HMMA split-bf16 GEMM, mixed-tail chunks, 3-stage pipe ----
// EPI 0: C = v + bias[n] (fp32) | EPI 2: C = relu(v + bias[n]) (fp32)
// EPI 3: C = v + bias[n] stored as __half (C reinterpreted)
// EPI 1: v += cc0[m]*bias[n]+cc1[m]*b1[n], packed split bf16 -> OS (WH layout)
#define ROWB 144
template<int KF, int REM, int NKW, int EPI>
__global__ void __launch_bounds__(256, 2)
gemm_mma(const __nv_bfloat16* __restrict__ A_, int lda,
         const __nv_bfloat16* __restrict__ B_, int ldb, int Ncols,
         float* __restrict__ C_, int ldc, const float* __restrict__ bias_,
         __nv_bfloat16* __restrict__ OS,
         const int* __restrict__ cc0, const int* __restrict__ cc1,
         const float* __restrict__ b1,
         const __nv_bfloat16* A2, const __nv_bfloat16* B2,
         float* C2, const float* bias2) {
    constexpr int CF = KF / 64;
    constexpr int PER = 3 * CF + REM;
    constexpr int NCH = NKW * PER;
    constexpr int W = 2 * KF + REM * 64;
    constexpr int APT = 2 * CF + REM;
    constexpr int STG = 128 * ROWB;
    constexpr int BBASE = 3 * STG;
    extern __shared__ char smem[];
    const uint32_t sb = smem_u32(smem);
    const int tid = threadIdx.x, lane = tid & 31, wid = tid >> 5;
    const int m0 = blockIdx.y * 128, n0 = blockIdx.x * 128;
    const int wm = wid >> 1, wn = wid & 1;

    const __nv_bfloat16* A = A_;
    const __nv_bfloat16* Bw = B_;
    float* C = C_;
    const float* bias = bias_;
    if (blockIdx.z == 1) { A = A2; Bw = B2; C = C2; bias = bias2; }

    float acc[2][8][4];
#pragma unroll
    for (int i = 0; i < 2; i++)
#pragma unroll
        for (int j = 0; j < 8; j++)
#pragma unroll
            for (int k = 0; k < 4; k++) acc[i][j][k] = 0.f;

    auto chunk_map = [&](int i, int& aoff, int& boff, int& kwv, bool& anew, int& aid) {
        int kw = i / PER;
        int r = i - kw * PER;
        int al;
        if (r < 2 * CF) {
            int pi = r >> 1;
            anew = ((r & 1) == 0);
            al = pi;
            aoff = pi * 64;
            boff = ((r & 1) ? KF : 0) + pi * 64;
        } else if (r < 3 * CF) {
            int c = r - 2 * CF;
            anew = true;
            al = CF + c;
            aoff = KF + c * 64;
            boff = c * 64;
        } else {
            anew = true;
            al = 2 * CF;
            aoff = 2 * KF;
            boff = 2 * KF;
        }
        kwv = kw;
        aid = kw * APT + al;
        boff += kw * W;
    };

    auto load_stage = [&](int i) {
        int aoff, boff, kwv, aid; bool anew;
        chunk_map(i, aoff, boff, kwv, anew, aid);
        if (anew) {
            uint32_t sA = sb + (aid % 3) * STG;
#pragma unroll
            for (int t = 0; t < 4; t++) {
                int idx = tid + t * 256;
                int row = idx >> 3, j = idx & 7;
                const __nv_bfloat16* src = A + (size_t)(m0 + row + kwv) * lda + aoff + j * 8;
                CP_ASYNC16(sA + row * ROWB + j * 16, src);
            }
        }
        uint32_t sB = sb + BBASE + (i % 3) * STG;
#pragma unroll
        for (int t = 0; t < 4; t++) {
            int idx = tid + t * 256;
            int row = idx >> 3, j = idx & 7;
            int n = n0 + row;
            int ok = (n < Ncols);
            const __nv_bfloat16* src = Bw + (size_t)(ok ? n : 0) * ldb + boff + j * 8;
            CP_ASYNC16Z(sB + row * ROWB + j * 16, src, ok ? 16 : 0);
        }
        CP_COMMIT();
    };

    const uint32_t aLane = (uint32_t)((wm * 32 + (lane & 15)) * ROWB + ((lane >> 4) * 8) * 2);
    const uint32_t bLane = (uint32_t)((wn * 64 + (lane & 7) + ((lane >> 4) * 8)) * ROWB +
                                      (((lane >> 3) & 1) * 8) * 2);

    load_stage(0);
    load_stage(1);
    for (int i = 0; i < NCH; i++) {
        if (i + 1 < NCH) { CP_WAIT(1); }
        else             { CP_WAIT(0); }
        __syncthreads();
        int aoff, boff, kwv, aid; bool anew;
        chunk_map(i, aoff, boff, kwv, anew, aid);
        uint32_t aB = sb + (aid % 3) * STG + aLane;
        uint32_t bB = sb + BBASE + (i % 3) * STG + bLane;
#pragma unroll
        for (int ks = 0; ks < 4; ks++) {
            uint32_t a0[4], a1[4], bf[4][4];
            LDSM4(a0, aB + ks * 32);
            LDSM4(a1, aB + 16 * ROWB + ks * 32);
#pragma unroll
            for (int j = 0; j < 4; j++)
                LDSM4(bf[j], bB + j * 16 * ROWB + ks * 32);
#pragma unroll
            for (int j = 0; j < 4; j++) {
                MMA16816(acc[0][2 * j],     a0, bf[j][0], bf[j][1]);
                MMA16816(acc[0][2 * j + 1], a0, bf[j][2], bf[j][3]);
                MMA16816(acc[1][2 * j],     a1, bf[j][0], bf[j][1]);
                MMA16816(acc[1][2 * j + 1], a1, bf[j][2], bf[j][3]);
            }
        }
        if (i + 2 < NCH) load_stage(i + 2);
    }

    const int g = lane >> 2, tg = lane & 3;
#pragma unroll
    for (int mi = 0; mi < 2; mi++) {
        int mA = m0 + wm * 32 + mi * 16 + g;
#pragma unroll
        for (int nj = 0; nj < 8; nj++) {
            int n = n0 + wn * 64 + nj * 8 + tg * 2;
            float v0 = acc[mi][nj][0], v1 = acc[mi][nj][1];
            float v2 = acc[mi][nj][2], v3 = acc[mi][nj][3];
            if (EPI == 0 || EPI == 2) {
                if (n < Ncols) {
                    float bn = bias[n], bn1 = bias[n + 1];
                    v0 += bn; v1 += bn1; v2 += bn; v3 += bn1;
                    if (EPI == 2) {
                        v0 = fmaxf(v0, 0.f); v1 = fmaxf(v1, 0.f);
                        v2 = fmaxf(v2, 0.f); v3 = fmaxf(v3, 0.f);
                    }
                    *(float2*)&C[(size_t)mA * ldc + n] = make_float2(v0, v1);
                    *(float2*)&C[(size_t)(mA + 8) * ldc + n] = make_float2(v2, v3);
                }
            } else if (EPI == 3) {
                if (n < Ncols) {
                    float bn = bias[n], bn1 = bias[n + 1];
                    __half* Ch = (__half*)C;
                    *(__half2*)&Ch[(size_t)mA * ldc + n] = __floats2half2_rn(v0 + bn, v1 + bn1);
                    *(__half2*)&Ch[(size_t)(mA + 8) * ldc + n] = __floats2half2_rn(v2 + bn, v3 + bn1);
                }
            } else {
                if (n < 200) {
                    float bn = bias[n], bn1 = bias[n + 1];
                    float dn = b1[n], dn1 = b1[n + 1];
                    float q0a = (float)cc0[mA], q1a = (float)cc1[mA];
                    float q0b = (float)cc0[mA + 8], q1b = (float)cc1[mA + 8];
                    v0 += q0a * bn + q1a * dn;   v1 += q0a * bn1 + q1a * dn1;
                    v2 += q0b * bn + q1b * dn;   v3 += q0b * bn1 + q1b * dn1;
                    uint32_t hi0, lo0, hi1, lo1;
                    split_pair(v0, v1, hi0, lo0);
                    split_pair(v2, v3, hi1, lo1);
                    __nv_bfloat16* r0 = OS + (size_t)mA * WH;
                    __nv_bfloat16* r1 = OS + (size_t)(mA + 8) * WH;
                    if (n < 192) {
                        *(uint32_t*)&r0[n] = hi0;       *(uint32_t*)&r0[192 + n] = lo0;
                        *(uint32_t*)&r1[n] = hi1;       *(uint32_t*)&r1[192 + n] = lo1;
                    } else {
                        int q = n - 192;
                        *(uint32_t*)&r0[384 + q] = hi0; *(uint32_t*)&r0[392 + q] = lo0;
                        *(uint32_t*)&r0[400 + q] = hi0;
                        *(uint32_t*)&r1[384 + q] = hi1; *(uint32_t*)&r1[392 + q] = lo1;
                        *(uint32_t*)&r1[400 + q] = hi1;
                    }
                }
            }
        }
    }
}

// ---------------- preprocessing kernels ----------------
__global__ void k_init_h(const float* __restrict__ x, float* __restrict__ h,
                         __nv_bfloat16* __restrict__ hs0, __nv_bfloat16* __restrict__ hs1) {
    int idx = blockIdx.x * blockDim.x + threadIdx.x;
    if (idx >= (NN + 2) * WH) return;
    int n = idx / WH, j = idx - n * WH;
    __nv_bfloat16 z = __float2bfloat16(0.f);
    hs1[idx] = z;
    if (n >= NN) { hs0[idx] = z; return; }
    int ch = -1; bool ishi = true; bool firsthi = false;
    if (j < 192)      { ch = j; ishi = true; firsthi = true; }
    else if (j < 384) { ch = j - 192; ishi = false; }
    else {
        int p = j - 384;
        if (p < 8)       { ch = 192 + p; ishi = true; firsthi = true; }
        else if (p < 16) { ch = 192 + p - 8; ishi = false; }
        else if (p < 24) { ch = 192 + p - 16; ishi = true; }
    }
    if (ch < 0) { hs0[idx] = z; return; }
    float v = (ch < DD) ? x[(size_t)n * DD + ch] : 0.f;
    if (firsthi) h[(size_t)n * HH + ch] = v;
    __nv_bfloat16 hi, lo;
    split2(v, hi, lo);
    hs0[idx] = ishi ? hi : lo;
}

__global__ void k_zero_as(__nv_bfloat16* __restrict__ as_) {
    int idx = blockIdx.x * blockDim.x + threadIdx.x;
    if (idx >= NN * 20) return;
    int n = idx / 20, c = (idx - n * 20) * 2;
    *(uint32_t*)&as_[(size_t)n * WH + 408 + c] = 0;
}

__global__ void k_count(const int* __restrict__ eidx, const int* __restrict__ etyp,
                        int* __restrict__ cnt) {
    int e = blockIdx.x * blockDim.x + threadIdx.x;
    if (e >= EE) return;
    int d = eidx[EE + e] + (etyp[e] ? NN : 0);
    atomicAdd(&cnt[d], 1);
}

__global__ void k_scan1(const int* __restrict__ cnt, int* __restrict__ part) {
    __shared__ int sh[1024];
    int t = threadIdx.x;
    int v = cnt[blockIdx.x * 1024 + t];
    sh[t] = v;
    __syncthreads();
    for (int off = 512; off > 0; off >>= 1) {
        if (t < off) sh[t] += sh[t + off];
        __syncthreads();
    }
    if (t == 0) part[blockIdx.x] = sh[0];
}

__global__ void k_scan2(const int* __restrict__ part, int* __restrict__ pref,
                        int* __restrict__ rowptr) {
    __shared__ int sh[256];
    int t = threadIdx.x;
    int v = (t < 200) ? part[t] : 0;
    sh[t] = v;
    __syncthreads();
    for (int off = 1; off < 256; off <<= 1) {
        int u = (t >= off) ? sh[t - off] : 0;
        __syncthreads();
        sh[t] += u;
        __syncthreads();
    }
    if (t < 200) pref[t] = sh[t] - v;
    if (t == 0) rowptr[2 * NN] = EE;
}

__global__ void k_scan3(const int* __restrict__ cnt, const int* __restrict__ pref,
                        int* __restrict__ rowptr, int* __restrict__ rowfill) {
    __shared__ int sh[1024];
    int t = threadIdx.x;
    int i = blockIdx.x * 1024 + t;
    int v = cnt[i];
    sh[t] = v;
    __syncthreads();
    for (int off = 1; off < 1024; off <<= 1) {
        int u = (t >= off) ? sh[t - off] : 0;
        __syncthreads();
        sh[t] += u;
        __syncthreads();
    }
    int excl = sh[t] - v + pref[blockIdx.x];
    rowptr[i] = excl;
    rowfill[i] = excl;
}

__global__ void k_fill(const int* __restrict__ eidx, const int* __restrict__ etyp,
                       int* __restrict__ rowfill, int* __restrict__ col) {
    int e = blockIdx.x * blockDim.x + threadIdx.x;
    if (e >= EE) return;
    int d = eidx[EE + e] + (etyp[e] ? NN : 0);
    int p = atomicAdd(&rowfill[d], 1);
    col[p] = eidx[e];
}

__global__ void k_packw(const float* __restrict__ src, __nv_bfloat16* __restrict__ dst,
                        int O, int I, int KW) {
    int KFw = (I / 64) * 64;
    int rem = I - KFw;
    int Wd = 2 * KFw + (rem ? 64 : 0);
    int idx = blockIdx.x * blockDim.x + threadIdx.x;
    if (idx >= O * KW * Wd) return;
    int o = idx / (KW * Wd);
    int r = idx - o * (KW * Wd);
    int kw = r / Wd, j = r - kw * Wd;
    int ch = -1; bool ishi = true;
    if (j < KFw)          { ch = j; ishi = true; }
    else if (j < 2 * KFw) { ch = j - KFw; ishi = false; }
    else {
        int p = j - 2 * KFw;
        if (p < rem)          { ch = KFw + p; ishi = true; }
        else if (p < 2 * rem) { ch = KFw + p - rem; ishi = true; }
        else if (p < 3 * rem) { ch = KFw + p - 2 * rem; ishi = false; }
    }
    __nv_bfloat16 outv = __float2bfloat16(0.f);
    if (ch >= 0) {
        float v = src[((size_t)o * I + ch) * KW + kw];
        __nv_bfloat16 hi, lo;
        split2(v, hi, lo);
        outv = ishi ? hi : lo;
    }
    dst[(size_t)o * (KW * Wd) + (size_t)kw * Wd + j] = outv;
}

__global__ void k_wcat_pack(const float* __restrict__ gW, __nv_bfloat16* __restrict__ dst) {
    int idx = blockIdx.x * blockDim.x + threadIdx.x;
    if (idx >= 200 * WS) return;
    int o = idx / WS, j = idx - o * WS;
    int ch = -1; bool ishi = true;
    if (j < 384)      { ch = j; ishi = true; }
    else if (j < 768) { ch = j - 384; ishi = false; }
    else {
        int p = j - 768;
        if (p < 16)      { ch = 384 + p; ishi = true; }
        else if (p < 32) { ch = 384 + p - 16; ishi = true; }
        else if (p < 48) { ch = 384 + p - 32; ishi = false; }
    }
    __nv_bfloat16 outv = __float2bfloat16(0.f);
    if (ch >= 0) {
        float v = (ch < 200) ? gW[(size_t)o * 200 + ch]
                             : gW[(size_t)200 * 200 + (size_t)o * 200 + (ch - 200)];
        __nv_bfloat16 hi, lo;
        split2(v, hi, lo);
        outv = ishi ? hi : lo;
    }
    dst[idx] = outv;
}

// ---------------- gather: 64-thread group per (node, etype) -> WS rows ------
__global__ void k_gather(const float* __restrict__ h, const int* __restrict__ rowptr,
                         const int* __restrict__ col, __nv_bfloat16* __restrict__ s) {
    int gid = (blockIdx.x * blockDim.x + threadIdx.x) >> 6;
    int t = threadIdx.x & 63;
    if (gid >= 2 * NN) return;
    int node = (gid < NN) ? gid : gid - NN;
    int ty   = (gid < NN) ? 0 : 1;
    bool act = (t < 50);
    float4 a = make_float4(0.f, 0.f, 0.f, 0.f);
    int beg = rowptr[gid], end = rowptr[gid + 1];
    int e = beg;
    for (; e + 4 <= end; e += 4) {
        int c0 = __ldg(&col[e]), c1 = __ldg(&col[e + 1]);
        int c2 = __ldg(&col[e + 2]), c3 = __ldg(&col[e + 3]);
        if (act) {
            float4 v0 = __ldg(reinterpret_cast<const float4*>(h + (size_t)c0 * HH) + t);
            float4 v1 = __ldg(reinterpret_cast<const float4*>(h + (size_t)c1 * HH) + t);
            float4 v2 = __ldg(reinterpret_cast<const float4*>(h + (size_t)c2 * HH) + t);
            float4 v3 = __ldg(reinterpret_cast<const float4*>(h + (size_t)c3 * HH) + t);
            a.x += v0.x + v1.x + v2.x + v3.x;
            a.y += v0.y + v1.y + v2.y + v3.y;
            a.z += v0.z + v1.z + v2.z + v3.z;
            a.w += v0.w + v1.w + v2.w + v3.w;
        }
    }
    if (e + 2 <= end) {
        int c0 = __ldg(&col[e]), c1 = __ldg(&col[e + 1]);
        if (act) {
            float4 v0 = __ldg(reinterpret_cast<const float4*>(h + (size_t)c0 * HH) + t);
            float4 v1 = __ldg(reinterpret_cast<const float4*>(h + (size_t)c1 * HH) + t);
            a.x += v0.x + v1.x; a.y += v0.y + v1.y;
            a.z += v0.z + v1.z; a.w += v0.w + v1.w;
        }
        e += 2;
    }
    if (e < end) {
        int c0 = __ldg(&col[e]);
        if (act) {
            float4 v = __ldg(reinterpret_cast<const float4*>(h + (size_t)c0 * HH) + t);
            a.x += v.x; a.y += v.y; a.z += v.z; a.w += v.w;
        }
    }
    __nv_bfloat16* sr = s + (size_t)node * WS;
    if (act) {
        int ch = ty * 200 + 4 * t;
        uint32_t hiA, loA, hiB, loB;
        split_pair(a.x, a.y, hiA, loA);
        split_pair(a.z, a.w, hiB, loB);
        if (ch < 384) {
            *(uint32_t*)&sr[ch] = hiA;        *(uint32_t*)&sr[ch + 2] = hiB;
            *(uint32_t*)&sr[384 + ch] = loA;  *(uint32_t*)&sr[384 + ch + 2] = loB;
        } else {
            int q = ch - 384;
            *(uint32_t*)&sr[768 + q] = hiA;   *(uint32_t*)&sr[768 + q + 2] = hiB;
            *(uint32_t*)&sr[784 + q] = loA;   *(uint32_t*)&sr[784 + q + 2] = loB;
            *(uint32_t*)&sr[800 + q] = hiA;   *(uint32_t*)&sr[800 + q + 2] = hiB;
        }
    } else if (ty == 1 && t >= 50 && t < 54) {
        int c = 816 + (t - 50) * 4;
        *(uint32_t*)&sr[c] = 0;
        *(uint32_t*)&sr[c + 2] = 0;
    }
}

// float4 GRU over half gi/gh, writes WH-layout split rows
__global__ void k_gru(const __half* __restrict__ gi, const __half* __restrict__ gh,
                      const float* __restrict__ h, float* __restrict__ hn,
                      __nv_bfloat16* __restrict__ hns) {
    int idx = blockIdx.x * blockDim.x + threadIdx.x;
    if (idx >= NN * 50) return;
    int n = idx / 50, c = (idx - n * 50) * 4;
    size_t base = (size_t)n * 600 + c;
    float4 ir  = ldh4(gi + base);
    float4 iz  = ldh4(gi + base + 200);
    float4 inn = ldh4(gi + base + 400);
    float4 hr  = ldh4(gh + base);
    float4 hz  = ldh4(gh + base + 200);
    float4 hnn = ldh4(gh + base + 400);
    float4 hv  = *(const float4*)&h[(size_t)n * HH + c];
    float4 o;
    o.x = (1.f - fsigmoid(iz.x + hz.x)) * ftanh(inn.x + fsigmoid(ir.x + hr.x) * hnn.x) + fsigmoid(iz.x + hz.x) * hv.x;
    o.y = (1.f - fsigmoid(iz.y + hz.y)) * ftanh(inn.y + fsigmoid(ir.y + hr.y) * hnn.y) + fsigmoid(iz.y + hz.y) * hv.y;
    o.z = (1.f - fsigmoid(iz.z + hz.z)) * ftanh(inn.z + fsigmoid(ir.z + hr.z) * hnn.z) + fsigmoid(iz.z + hz.z) * hv.z;
    o.w = (1.f - fsigmoid(iz.w + hz.w)) * ftanh(inn.w + fsigmoid(ir.w + hr.w) * hnn.w) + fsigmoid(iz.w + hz.w) * hv.w;
    *(float4*)&hn[(size_t)n * HH + c] = o;
    uint32_t hi0, lo0, hi1, lo1;
    split_pair(o.x, o.y, hi0, lo0);
    split_pair(o.z, o.w, hi1, lo1);
    __nv_bfloat16* hp = hns + (size_t)n * WH;
    if (c < 192) {
        *(uint32_t*)&hp[c] = hi0;        *(uint32_t*)&hp[c + 2] = hi1;
        *(uint32_t*)&hp[192 + c] = lo0;  *(uint32_t*)&hp[192 + c + 2] = lo1;
    } else {
        int q = c - 192;
        *(uint32_t*)&hp[384 + q] = hi0;  *(uint32_t*)&hp[384 + q + 2] = hi1;
        *(uint32_t*)&hp[392 + q] = lo0;  *(uint32_t*)&hp[392 + q + 2] = lo1;
        *(uint32_t*)&hp[400 + q] = hi0;  *(uint32_t*)&hp[400 + q + 2] = hi1;
    }
}

// concat(x, h) -> WC rows (K=320 exact, [hi|lo])
__global__ void k_catsplit(const float* __restrict__ x, const float* __restrict__ h,
                           __nv_bfloat16* __restrict__ dst) {
    int idx = blockIdx.x * blockDim.x + threadIdx.x;
    if (idx >= (NN + 2) * 160) return;
    int n = idx / 160, c = (idx - n * 160) * 2;
    float v0 = 0.f, v1 = 0.f;
    if (n < NN) {
        if (c < DD) {
            float2 xv = *(const float2*)&x[(size_t)n * DD + c];
            v0 = xv.x; v1 = xv.y;
        } else {
            float2 hvv = *(const float2*)&h[(size_t)n * HH + (c - DD)];
            v0 = hvv.x; v1 = hvv.y;
        }
    }
    uint32_t hiw, low;
    split_pair(v0, v1, hiw, low);
    *(uint32_t*)&dst[(size_t)n * WC + c] = hiw;
    *(uint32_t*)&dst[(size_t)n * WC + 320 + c] = low;
}

__device__ __forceinline__ int map_wh(int j, bool& ishi) {
    if (j < 192)      { ishi = true;  return j; }
    if (j < 384)      { ishi = false; return j - 192; }
    int p = j - 384;
    if (p < 8)        { ishi = true;  return 192 + p; }
    if (p < 16)       { ishi = false; return 192 + p - 8; }
    if (p < 24)       { ishi = true;  return 192 + p - 16; }
    return -1;
}

__global__ void k_pool3y(const float* __restrict__ in, __nv_bfloat16* __restrict__ out) {
    int idx = blockIdx.x * blockDim.x + threadIdx.x;
    if (idx >= (MP + 2) * 224) return;
    int m = idx / 224, j = (idx - m * 224) * 2;
    bool ishi;
    int ch = map_wh(j, ishi);
    float v0 = 0.f, v1 = 0.f;
    if (m < MP && ch >= 0) {
        int b = m / 198, l = m - b * 198;
        size_t base = ((size_t)b * 400 + 2 * l) * 200 + ch;
        float2 p0 = *(const float2*)&in[base];
        float2 p1 = *(const float2*)&in[base + 200];
        float2 p2 = *(const float2*)&in[base + 400];
        v0 = fmaxf(fmaxf(p0.x, p1.x), p2.x);
        v1 = fmaxf(fmaxf(p0.y, p1.y), p2.y);
    }
    uint32_t hiw, low;
    split_pair(v0, v1, hiw, low);
    *(uint32_t*)&out[(size_t)m * WH + j] = ishi ? hiw : low;
}

__global__ void k_pool2y(const float* __restrict__ in, __nv_bfloat16* __restrict__ out) {
    int idx = blockIdx.x * blockDim.x + threadIdx.x;
    if (idx >= M2 * 224) return;
    int m = idx / 224, j = (idx - m * 224) * 2;
    bool ishi;
    int ch = map_wh(j, ishi);
    float v0 = 0.f, v1 = 0.f;
    if (ch >= 0) {
        int b = m / 99, l = m - b * 99;
        size_t base = ((size_t)b * 198 + 2 * l) * 200 + ch;
        float2 p0 = *(const float2*)&in[base];
        float2 p1 = *(const float2*)&in[base + 200];
        v0 = fmaxf(p0.x, p1.x);
        v1 = fmaxf(p0.y, p1.y);
    }
    uint32_t hiw, low;
    split_pair(v0, v1, hiw, low);
    *(uint32_t*)&out[(size_t)m * WH + j] = ishi ? hiw : low;
}

__global__ void k_pool3z(const float* __restrict__ in, __nv_bfloat16* __restrict__ out) {
    int idx = blockIdx.x * blockDim.x + threadIdx.x;
    if (idx >= (MP + 2) * 160) return;
    int m = idx / 160, c = (idx - m * 160) * 2;
    float v0 = 0.f, v1 = 0.f;
    if (m < MP) {
        int b = m / 198, l = m - b * 198;
        size_t base = ((size_t)b * 400 + 2 * l) * 320 + c;
        float2 p0 = *(const float2*)&in[base];
        float2 p1 = *(const float2*)&in[base + 320];
        float2 p2 = *(const float2*)&in[base + 640];
        v0 = fmaxf(fmaxf(p0.x, p1.x), p2.x);
        v1 = fmaxf(fmaxf(p0.y, p1.y), p2.y);
    }
    uint32_t hiw, low;
    split_pair(v0, v1, hiw, low);
    *(uint32_t*)&out[(size_t)m * WC + c] = hiw;
    *(uint32_t*)&out[(size_t)m * WC + 320 + c] = low;
}

__global__ void k_pool2z(const float* __restrict__ in, __nv_bfloat16* __restrict__ out) {
    int idx = blockIdx.x * blockDim.x + threadIdx.x;
    if (idx >= M2 * 160) return;
    int m = idx / 160, c = (idx - m * 160) * 2;
    int b = m / 99, l = m - b * 99;
    size_t base = ((size_t)b * 198 + 2 * l) * 320 + c;
    float2 p0 = *(const float2*)&in[base];
    float2 p1 = *(const float2*)&in[base + 320];
    float v0 = fmaxf(p0.x, p1.x);
    float v1 = fmaxf(p0.y, p1.y);
    uint32_t hiw, low;
    split_pair(v0, v1, hiw, low);
    *(uint32_t*)&out[(size_t)m * WC + c] = hiw;
    *(uint32_t*)&out[(size_t)m * WC + 320 + c] = low;
}

__global__ void k_avg(const float* __restrict__ yp, const float* __restrict__ zp,
                      float* __restrict__ avg) {
    int idx = blockIdx.x * blockDim.x + threadIdx.x;
    if (idx >= BB * 64) return;
    int j = (idx & 63) * 4;
    int b = idx >> 6;
    float4 s = make_float4(0.f, 0.f, 0.f, 0.f);
    for (int l = 0; l < 99; l++) {
        size_t off = ((size_t)b * 99 + l) * 256 + j;
        float4 yv = *(const float4*)&yp[off];
        float4 zv = *(const float4*)&zp[off];
        s.x += yv.x * zv.x; s.y += yv.y * zv.y;
        s.z += yv.z * zv.z; s.w += yv.w * zv.w;
    }
    const float inv = 1.f / 99.f;
    s.x *= inv; s.y *= inv; s.z *= inv; s.w *= inv;
    *(float4*)&avg[(size_t)b * 256 + j] = s;
}

// ---------------- tiny SIMT head GEMM (optional 2nd output C2h) ----------
template<int EPI>
__global__ __launch_bounds__(256)
void gemm_tn(const float* __restrict__ A, const float* __restrict__ W,
             const float* __restrict__ bias, float* __restrict__ C,
             int M, int Nc, int K, float* __restrict__ C2h) {
    __shared__ float As[8][128];
    __shared__ float Ws[8][64];
    int tid = threadIdx.x;
    int m0 = blockIdx.y * 128;
    int n0 = blockIdx.x * 64;
    int msub = (tid >> 4) * 8;
    int nsub = (tid & 15) * 4;
    float acc[8][4];
#pragma unroll
    for (int i = 0; i < 8; i++)
#pragma unroll
        for (int j = 0; j < 4; j++) acc[i][j] = 0.f;
    int la_m = tid >> 1;
    int la_k = (tid & 1) * 4;
    int lw_n = tid >> 2;
    int lw_k = (tid & 3) * 2;
    for (int k0 = 0; k0 < K; k0 += 8) {
        float4 av = *(const float4*)(A + (size_t)(m0 + la_m) * K + k0 + la_k);
        As[la_k + 0][la_m] = av.x;
        As[la_k + 1][la_m] = av.y;
        As[la_k + 2][la_m] = av.z;
        As[la_k + 3][la_m] = av.w;
        float2 wv = make_float2(0.f, 0.f);
        if (n0 + lw_n < Nc)
            wv = *(const float2*)(W + (size_t)(n0 + lw_n) * K + k0 + lw_k);
        Ws[lw_k + 0][lw_n] = wv.x;
        Ws[lw_k + 1][lw_n] = wv.y;
        __syncthreads();
#pragma unroll
        for (int k = 0; k < 8; k++) {
            float4 a0 = *(const float4*)&As[k][msub];
            float4 a1 = *(const float4*)&As[k][msub + 4];
            float4 bv = *(const float4*)&Ws[k][nsub];
            float am[8] = {a0.x, a0.y, a0.z, a0.w, a1.x, a1.y, a1.z, a1.w};
            float bn[4] = {bv.x, bv.y, bv.z, bv.w};
#pragma unroll
            for (int i = 0; i < 8; i++)
#pragma unroll
                for (int j = 0; j < 4; j++) acc[i][j] += am[i] * bn[j];
        }
        __syncthreads();
    }
#pragma unroll
    for (int i = 0; i < 8; i++) {
        int m = m0 + msub + i;
#pragma unroll
        for (int j = 0; j < 4; j++) {
            int n = n0 + nsub + j;
            if (n < Nc) {
                float v = acc[i][j] + bias[n];
                if (EPI == 1) v = fmaxf(v, 0.f);
                C[(size_t)m * Nc + n] = v;
                if (C2h) C2h[(size_t)m * Nc + n] = v;
            }
        }
    }
}

// ---------------- launcher ----------------
extern "C" void kernel_launch(void* const* d_in, const int* in_sizes, int n_in,
                              void* d_out, int out_size) {
    const float* x    = (const float*)d_in[0];
    const int*   eidx = (const int*)d_in[1];
    const int*   etyp = (const int*)d_in[2];
    const float* ggnnW = (const float*)d_in[3];
    const float* ggnnB = (const float*)d_in[4];
    const float* Wih  = (const float*)d_in[5];
    const float* Whh  = (const float*)d_in[6];
    const float* bih  = (const float*)d_in[7];
    const float* bhh  = (const float*)d_in[8];
    const float* c1w  = (const float*)d_in[9];
    const float* c1b  = (const float*)d_in[10];
    const float* c2w  = (const float*)d_in[11];
    const float* c2b  = (const float*)d_in[12];
    const float* cc1w = (const float*)d_in[13];
    const float* cc1b = (const float*)d_in[14];
    const float* cc2w = (const float*)d_in[15];
    const float* cc2b = (const float*)d_in[16];
    const float* yw   = (const float*)d_in[17];
    const float* yb   = (const float*)d_in[18];
    const float* zw   = (const float*)d_in[19];
    const float* zb   = (const float*)d_in[20];
    const float* l1w  = (const float*)d_in[21];
    const float* l1b  = (const float*)d_in[22];
    const float* f1w  = (const float*)d_in[23];
    const float* f1b  = (const float*)d_in[24];
    const float* f2w  = (const float*)d_in[25];
    const float* f2b  = (const float*)d_in[26];
    const float* clsw = (const float*)d_in[27];
    const float* clsb = (const float*)d_in[28];
    float* out = (float*)d_out;

    void* p;
#define GET(name, sym, T) cudaGetSymbolAddress(&p, sym); T* name = (T*)p;
    GET(h0, g_h0, float) GET(h1, g_h1, float)
    GET(h0s, g_h0s, __nv_bfloat16) GET(h1s, g_h1s, __nv_bfloat16)
    GET(ss, g_ss, __nv_bfloat16) GET(as, g_as, __nv_bfloat16)
    GET(gi, g_gi, __half) GET(gh, g_gh, __half)
    GET(cnt, g_cnt, int) GET(rowptr, g_rowptr, int) GET(rowfill, g_rowfill, int)
    GET(colv, g_col, int) GET(part, g_part, int) GET(pref, g_pref, int)
    GET(wcs, g_wcat_s, __nv_bfloat16) GET(wis, g_wih_s, __nv_bfloat16) GET(whs, g_whh_s, __nv_bfloat16)
    GET(mys, g_myw_s, __nv_bfloat16) GET(mzs, g_mzw_s, __nv_bfloat16)
    GET(c1p, g_c1p, __nv_bfloat16) GET(c2p, g_c2p, __nv_bfloat16)
    GET(cc1p, g_cc1p, __nv_bfloat16) GET(cc2p, g_cc2p, __nv_bfloat16)
    GET(xcat, g_xcat, __nv_bfloat16)
    GET(y1g, g_y1g, float) GET(z1g, g_z1g, float)
    GET(y1s, g_y1s, __nv_bfloat16) GET(z1s, g_z1s, __nv_bfloat16)
    GET(y2g, g_y2g, float) GET(z2g, g_z2g, float)
    GET(y2ps, g_y2ps, __nv_bfloat16) GET(z2ps, g_z2ps, __nv_bfloat16)
    GET(yp, g_yp, float) GET(zp, g_zp, float) GET(avg, g_avg, float)
    GET(m1, g_m1, float) GET(m2v, g_m2, float) GET(hfv, g_hf, float)
#undef GET

    const int SMEM = 6 * 128 * ROWB;   // 110592 (3 A + 3 B stages)
    cudaFuncSetAttribute(gemm_mma<384, 1, 1, 1>, cudaFuncAttributeMaxDynamicSharedMemorySize, SMEM);
    cudaFuncSetAttribute(gemm_mma<192, 1, 1, 3>, cudaFuncAttributeMaxDynamicSharedMemorySize, SMEM);
    cudaFuncSetAttribute(gemm_mma<192, 1, 3, 2>, cudaFuncAttributeMaxDynamicSharedMemorySize, SMEM);
    cudaFuncSetAttribute(gemm_mma<192, 1, 1, 2>, cudaFuncAttributeMaxDynamicSharedMemorySize, SMEM);
    cudaFuncSetAttribute(gemm_mma<320, 0, 3, 2>, cudaFuncAttributeMaxDynamicSharedMemorySize, SMEM);
    cudaFuncSetAttribute(gemm_mma<320, 0, 1, 2>, cudaFuncAttributeMaxDynamicSharedMemorySize, SMEM);
    cudaFuncSetAttribute(gemm_mma<192, 1, 1, 0>, cudaFuncAttributeMaxDynamicSharedMemorySize, SMEM);
    cudaFuncSetAttribute(gemm_mma<320, 0, 1, 0>, cudaFuncAttributeMaxDynamicSharedMemorySize, SMEM);

    // ---- preprocessing ----
    k_init_h<<<((NN + 2) * WH + 255) / 256, 256>>>(x, h0, h0s, h1s);
    k_zero_as<<<(NN * 20 + 255) / 256, 256>>>(as);
    cudaMemsetAsync(cnt, 0, 2 * NN * sizeof(int));
    k_count<<<EE / 256, 256>>>(eidx, etyp, cnt);
    k_scan1<<<200, 1024>>>(cnt, part);
    k_scan2<<<1, 256>>>(part, pref, rowptr);
    k_scan3<<<200, 1024>>>(cnt, pref, rowptr, rowfill);
    k_fill<<<EE / 256, 256>>>(eidx, etyp, rowfill, colv);
    k_wcat_pack<<<(200 * WS + 255) / 256, 256>>>(ggnnW, wcs);
    k_packw<<<(600 * WH + 255) / 256, 256>>>(Wih, wis, 600, 200, 1);
    k_packw<<<(600 * WH + 255) / 256, 256>>>(Whh, whs, 600, 200, 1);
    k_packw<<<(256 * WH + 255) / 256, 256>>>(yw, mys, 256, 200, 1);
    k_packw<<<(256 * WC + 255) / 256, 256>>>(zw, mzs, 256, 320, 1);
    k_packw<<<(200 * 3 * WH + 255) / 256, 256>>>(c1w, c1p, 200, 200, 3);
    k_packw<<<(200 * WH + 255) / 256, 256>>>(c2w, c2p, 200, 200, 1);
    k_packw<<<(320 * 3 * WC + 255) / 256, 256>>>(cc1w, cc1p, 320, 320, 3);
    k_packw<<<(320 * WC + 255) / 256, 256>>>(cc2w, cc2p, 320, 320, 1);

    // ---- GGNN steps ----
    for (int s = 0; s < NSTEPS; s++) {
        float* hin  = (s & 1) ? h1 : h0;
        float* hout = (s & 1) ? h0 : h1;
        __nv_bfloat16* hins  = (s & 1) ? h1s : h0s;
        __nv_bfloat16* houts = (s & 1) ? h0s : h1s;
        k_gather<<<2 * NN / 4, 256>>>(hin, rowptr, colv, ss);
        gemm_mma<384, 1, 1, 1><<<dim3(2, NN / 128), 256, SMEM>>>(
            ss, WS, wcs, WS, 200, nullptr, 0, ggnnB, as, cnt, cnt + NN, ggnnB + 200,
            ss, wcs, nullptr, ggnnB);
        // fused gi (z=0) + gh (z=1), half outputs
        gemm_mma<192, 1, 1, 3><<<dim3(5, NN / 128, 2), 256, SMEM>>>(
            as, WH, wis, WH, 600, (float*)gi, 600, bih, nullptr, nullptr, nullptr, nullptr,
            hins, whs, (float*)gh, bhh);
        k_gru<<<(NN * 50 + 255) / 256, 256>>>(gi, gh, hin, hout, houts);
    }
    // final h in h0 / h0s

    // ---- readout (all HMMA) ----
    k_catsplit<<<((NN + 2) * 160 + 255) / 256, 256>>>(x, h0, xcat);

    gemm_mma<192, 1, 3, 2><<<dim3(2, NN / 128), 256, SMEM>>>(
        h0s, WH, c1p, 3 * WH, 200, y1g, 200, c1b, nullptr, nullptr, nullptr, nullptr,
        h0s, c1p, y1g, c1b);
    k_pool3y<<<((MP + 2) * 224 + 255) / 256, 256>>>(y1g, y1s);
    gemm_mma<192, 1, 1, 2><<<dim3(2, MP / 128), 256, SMEM>>>(
        y1s, WH, c2p, WH, 200, y2g, 200, c2b, nullptr, nullptr, nullptr, nullptr,
        y1s, c2p, y2g, c2b);
    k_pool2y<<<(M2 * 224 + 255) / 256, 256>>>(y2g, y2ps);

    gemm_mma<320, 0, 3, 2><<<dim3(3, NN / 128), 256, SMEM>>>(
        xcat, WC, cc1p, 3 * WC, 320, z1g, 320, cc1b, nullptr, nullptr, nullptr, nullptr,
        xcat, cc1p, z1g, cc1b);
    k_pool3z<<<((MP + 2) * 160 + 255) / 256, 256>>>(z1g, z1s);
    gemm_mma<320, 0, 1, 2><<<dim3(3, MP / 128), 256, SMEM>>>(
        z1s, WC, cc2p, WC, 320, z2g, 320, cc2b, nullptr, nullptr, nullptr, nullptr,
        z1s, cc2p, z2g, cc2b);
    k_pool2z<<<(M2 * 160 + 255) / 256, 256>>>(z2g, z2ps);

    gemm_mma<192, 1, 1, 0><<<dim3(2, M2 / 128), 256, SMEM>>>(
        y2ps, WH, mys, WH, 256, yp, 256, yb, nullptr, nullptr, nullptr, nullptr,
        y2ps, mys, yp, yb);
    gemm_mma<320, 0, 1, 0><<<dim3(2, M2 / 128), 256, SMEM>>>(
        z2ps, WC, mzs, WC, 256, zp, 256, zb, nullptr, nullptr, nullptr, nullptr,
        z2ps, mzs, zp, zb);
    k_avg<<<(BB * 64 + 255) / 256, 256>>>(yp, zp, avg);

    // head: hf also written directly to out[512..], logits to out[0..512)
    gemm_tn<1><<<dim3(2, 2), 256>>>(avg, l1w, l1b, m1, BB, 128, 256, nullptr);
    gemm_tn<1><<<dim3(1, 2), 256>>>(m1, f1w, f1b, m2v, BB, 64, 128, nullptr);
    gemm_tn<1><<<dim3(2, 2), 256>>>(m2v, f2w, f2b, hfv, BB, 128, 64, out + BB * 2);
    gemm_tn<0><<<dim3(1, 2), 256>>>(hfv, clsw, clsb, out, BB, 2, 128, nullptr);
    (void)n_in; (void)in_sizes; (void)out_size;
}